// round 14
// baseline (speedup 1.0000x reference)
#include <cuda_runtime.h>
#include <cstdint>

// Problem constants (Pose_Loss: B=65536, D=154)
#define BB   65536
#define DD   154
#define N4   ((BB * DD) / 4)        // 2,523,136 float4s per array

#define BLOCK_THREADS 256
#define T4   512                    // float4s per array per tile
#define TILE_BYTES (T4 * 16)        // 8192 B per array per tile
#define NTILES (N4 / T4)            // 4928
#define GRID_BLOCKS 616
#define TPB (NTILES / GRID_BLOCKS)  // 8 contiguous tiles per block
#define PFD 2                       // prefetch distance (tiles)
static_assert(N4 == NTILES * T4, "exact");
static_assert(NTILES == GRID_BLOCKS * TPB, "perfect balance");

// Scratch (allocation-free device globals; zero at load, re-zeroed each exec)
__device__ double        g_acc[2];   // [0]=recon, [1]=KLD
__device__ int           g_count;
__device__ unsigned int  g_done;

__device__ __forceinline__ void l2_prefetch(const void* p) {
    asm volatile("prefetch.global.L2 [%0];" :: "l"(p));
}

__device__ __forceinline__ float2 row_weights(int l, int f) {
    // lr in {0,1,2}: use_l <=> l != 1 ; use_r <=> l != 0 ; gated by f != -1
    bool valid = (f != -1);
    return make_float2((valid && l != 1) ? 1.0f : 0.0f,
                       (valid && l != 0) ? 1.0f : 0.0f);
}

__global__ void __launch_bounds__(BLOCK_THREADS)
fused_pose_loss(const float4* __restrict__ rl, const float4* __restrict__ rr,
                const float4* __restrict__ kl, const float4* __restrict__ kr,
                const int* __restrict__ lr,    const int* __restrict__ fpose,
                float* __restrict__ out, int out_size) {
    const int tid = threadIdx.x;
    const unsigned gtid = blockIdx.x * BLOCK_THREADS + tid;

    // ---- Phase A: per-row count (616*256 = 157,696 threads > BB) ----
    int c = 0;
    if (gtid < BB) {
        int l = lr[gtid];
        if (fpose[gtid] != -1)
            c = (l != 1 ? 1 : 0) + (l != 0 ? 1 : 0);
    }

    // Each block owns TPB contiguous tiles.
    const unsigned t0 = blockIdx.x * TPB;

    // prefetch mapping: thread -> (array, line). 4 arrays x 64 lines = 256.
    const char* pf_base = (tid < 64)  ? (const char*)rl
                        : (tid < 128) ? (const char*)rr
                        : (tid < 192) ? (const char*)kl
                                      : (const char*)kr;
    const unsigned pf_line = (tid & 63) * 128;

    // prime: prefetch the first PFD tiles
    #pragma unroll
    for (int p = 0; p < PFD; p++)
        l2_prefetch(pf_base + (size_t)(t0 + p) * TILE_BYTES + pf_line);

    double racc = 0.0, kacc = 0.0;

    for (unsigned k = 0; k < TPB; k++) {
        const unsigned t = t0 + k;

        // prefetch tile k+PFD (keeps PFD tiles of DRAM requests queued)
        if (k + PFD < TPB)
            l2_prefetch(pf_base + (size_t)(t + PFD) * TILE_BYTES + pf_line);

        // batch all 8 loads (2 float4 per array) — should be L2 hits
        const unsigned i0 = t * T4 + tid;
        const unsigned i1 = i0 + BLOCK_THREADS;
        float4 a0 = rl[i0], a1 = rl[i1];
        float4 b0 = rr[i0], b1 = rr[i1];
        float4 c0 = kl[i0], c1 = kl[i1];
        float4 d0 = kr[i0], d1 = kr[i1];

        float rt = 0.0f, kt = 0.0f;
        #pragma unroll
        for (int j = 0; j < 2; j++) {
            unsigned i = j ? i1 : i0;
            float4 a = j ? a1 : a0;
            float4 b = j ? b1 : b0;
            float4 cc = j ? c1 : c0;
            float4 d = j ? d1 : d0;

            unsigned eb   = i * 4u;
            unsigned row0 = eb / DD;              // udiv -> mul-hi
            unsigned rem  = eb - row0 * DD;
            float2 w0 = row_weights(lr[row0], fpose[row0]);   // cache-resident

            if (rem <= (unsigned)(DD - 4)) {
                rt += w0.x * ((a.x + a.y) + (a.z + a.w))
                    + w0.y * ((b.x + b.y) + (b.z + b.w));
                kt += w0.x * ((cc.x + cc.y) + (cc.z + cc.w))
                    + w0.y * ((d.x + d.y) + (d.z + d.w));
            } else {
                float2 w1 = row_weights(lr[row0 + 1], fpose[row0 + 1]);
                float ae[4] = {a.x, a.y, a.z, a.w};
                float be[4] = {b.x, b.y, b.z, b.w};
                float ce[4] = {cc.x, cc.y, cc.z, cc.w};
                float de[4] = {d.x, d.y, d.z, d.w};
                #pragma unroll
                for (int e = 0; e < 4; e++) {
                    float2 w = ((rem + e) >= (unsigned)DD) ? w1 : w0;
                    rt += w.x * ae[e] + w.y * be[e];
                    kt += w.x * ce[e] + w.y * de[e];
                }
            }
        }
        racc += (double)rt;
        kacc += (double)kt;
    }

    // ---- Phase C: block reduction ----
    #pragma unroll
    for (int off = 16; off > 0; off >>= 1) {
        racc += __shfl_down_sync(0xFFFFFFFFu, racc, off);
        kacc += __shfl_down_sync(0xFFFFFFFFu, kacc, off);
        c    += __shfl_down_sync(0xFFFFFFFFu, c,    off);
    }

    __shared__ double s_r[8], s_k[8];
    __shared__ int    s_c[8];
    int wid = tid >> 5;
    int lid = tid & 31;
    if (lid == 0) { s_r[wid] = racc; s_k[wid] = kacc; s_c[wid] = c; }
    __syncthreads();

    if (wid == 0) {
        double br = (lid < 8) ? s_r[lid] : 0.0;
        double bk = (lid < 8) ? s_k[lid] : 0.0;
        int    bc = (lid < 8) ? s_c[lid] : 0;
        #pragma unroll
        for (int off = 4; off > 0; off >>= 1) {
            br += __shfl_down_sync(0xFFFFFFFFu, br, off);
            bk += __shfl_down_sync(0xFFFFFFFFu, bk, off);
            bc += __shfl_down_sync(0xFFFFFFFFu, bc, off);
        }
        if (lid == 0) {
            atomicAdd(&g_acc[0], br);
            atomicAdd(&g_acc[1], bk);
            if (bc) atomicAdd(&g_count, bc);
        }
    }

    // ---- Phase D: last-block finalize + reset ----
    __shared__ bool is_last;
    if (tid == 0) {
        __threadfence();
        unsigned tkt = atomicAdd(&g_done, 1u);
        is_last = (tkt == gridDim.x - 1);
    }
    __syncthreads();
    if (is_last && tid == 0) {
        __threadfence();
        double vr = g_acc[0];
        double vk = g_acc[1];
        int    vc = g_count;
        if (out_size > 0) out[0] = (float)(vr / 154.0);
        if (out_size > 1) out[1] = (float)vk;
        if (out_size > 2) out[2] = (float)vc;
        g_acc[0] = 0.0;
        g_acc[1] = 0.0;
        g_count  = 0;
        __threadfence();
        g_done   = 0;
    }
}

extern "C" void kernel_launch(void* const* d_in, const int* in_sizes, int n_in,
                              void* d_out, int out_size) {
    const float4* rl = (const float4*)d_in[0];
    const float4* rr = (const float4*)d_in[1];
    const float4* kl = (const float4*)d_in[2];
    const float4* kr = (const float4*)d_in[3];
    const int* lr    = (const int*)d_in[4];
    const int* fpose = (const int*)d_in[5];
    float* out = (float*)d_out;

    fused_pose_loss<<<GRID_BLOCKS, BLOCK_THREADS>>>(rl, rr, kl, kr, lr, fpose,
                                                    out, out_size);
}

// round 15
// speedup vs baseline: 1.2391x; 1.2391x over previous
#include <cuda_runtime.h>
#include <cstdint>

// Problem constants (Pose_Loss: B=65536, D=154)
#define BB   65536
#define DD   154
#define N4   ((BB * DD) / 4)        // 2,523,136 float4s per array

#define BLOCK_THREADS 256
#define T4   512                    // float4s per array per tile
#define TILE_BYTES (T4 * 16)        // 8192 B per array per tile
#define NTILES (N4 / T4)            // 4928
#define GRID_BLOCKS 448             // R13 config: single wave, 11 tiles/block
#define TPB (NTILES / GRID_BLOCKS)  // 11 contiguous tiles per block
#define PFD 2                       // ONLY change vs R13: prefetch distance 1->2
static_assert(N4 == NTILES * T4, "exact");
static_assert(NTILES == GRID_BLOCKS * TPB, "perfect balance");

// Scratch (allocation-free device globals; zero at load, re-zeroed each exec)
__device__ double        g_acc[2];   // [0]=recon, [1]=KLD
__device__ int           g_count;
__device__ unsigned int  g_done;

__device__ __forceinline__ void l2_prefetch(const void* p) {
    asm volatile("prefetch.global.L2 [%0];" :: "l"(p));
}

__device__ __forceinline__ float2 row_weights(int l, int f) {
    // lr in {0,1,2}: use_l <=> l != 1 ; use_r <=> l != 0 ; gated by f != -1
    bool valid = (f != -1);
    return make_float2((valid && l != 1) ? 1.0f : 0.0f,
                       (valid && l != 0) ? 1.0f : 0.0f);
}

__global__ void __launch_bounds__(BLOCK_THREADS)
fused_pose_loss(const float4* __restrict__ rl, const float4* __restrict__ rr,
                const float4* __restrict__ kl, const float4* __restrict__ kr,
                const int* __restrict__ lr,    const int* __restrict__ fpose,
                float* __restrict__ out, int out_size) {
    const int tid = threadIdx.x;
    const unsigned gtid = blockIdx.x * BLOCK_THREADS + tid;

    // ---- Phase A: per-row count (448*256 = 114,688 threads > BB) ----
    int c = 0;
    if (gtid < BB) {
        int l = lr[gtid];
        if (fpose[gtid] != -1)
            c = (l != 1 ? 1 : 0) + (l != 0 ? 1 : 0);
    }

    // Each block owns TPB contiguous tiles.
    const unsigned t0 = blockIdx.x * TPB;

    // prefetch mapping: thread -> (array, line). 4 arrays x 64 lines = 256.
    const char* pf_base = (tid < 64)  ? (const char*)rl
                        : (tid < 128) ? (const char*)rr
                        : (tid < 192) ? (const char*)kl
                                      : (const char*)kr;
    const unsigned pf_line = (tid & 63) * 128;

    // prime: prefetch the first PFD tiles
    #pragma unroll
    for (int p = 0; p < PFD; p++)
        l2_prefetch(pf_base + (size_t)(t0 + p) * TILE_BYTES + pf_line);

    double racc = 0.0, kacc = 0.0;

    for (unsigned k = 0; k < TPB; k++) {
        const unsigned t = t0 + k;

        // prefetch tile k+PFD (keeps PFD tiles of DRAM requests queued)
        if (k + PFD < TPB)
            l2_prefetch(pf_base + (size_t)(t + PFD) * TILE_BYTES + pf_line);

        // batch all 8 loads (2 float4 per array) — should be L2 hits
        const unsigned i0 = t * T4 + tid;
        const unsigned i1 = i0 + BLOCK_THREADS;
        float4 a0 = rl[i0], a1 = rl[i1];
        float4 b0 = rr[i0], b1 = rr[i1];
        float4 c0 = kl[i0], c1 = kl[i1];
        float4 d0 = kr[i0], d1 = kr[i1];

        float rt = 0.0f, kt = 0.0f;
        #pragma unroll
        for (int j = 0; j < 2; j++) {
            unsigned i = j ? i1 : i0;
            float4 a = j ? a1 : a0;
            float4 b = j ? b1 : b0;
            float4 cc = j ? c1 : c0;
            float4 d = j ? d1 : d0;

            unsigned eb   = i * 4u;
            unsigned row0 = eb / DD;              // udiv -> mul-hi
            unsigned rem  = eb - row0 * DD;
            float2 w0 = row_weights(lr[row0], fpose[row0]);   // cache-resident

            if (rem <= (unsigned)(DD - 4)) {
                rt += w0.x * ((a.x + a.y) + (a.z + a.w))
                    + w0.y * ((b.x + b.y) + (b.z + b.w));
                kt += w0.x * ((cc.x + cc.y) + (cc.z + cc.w))
                    + w0.y * ((d.x + d.y) + (d.z + d.w));
            } else {
                float2 w1 = row_weights(lr[row0 + 1], fpose[row0 + 1]);
                float ae[4] = {a.x, a.y, a.z, a.w};
                float be[4] = {b.x, b.y, b.z, b.w};
                float ce[4] = {cc.x, cc.y, cc.z, cc.w};
                float de[4] = {d.x, d.y, d.z, d.w};
                #pragma unroll
                for (int e = 0; e < 4; e++) {
                    float2 w = ((rem + e) >= (unsigned)DD) ? w1 : w0;
                    rt += w.x * ae[e] + w.y * be[e];
                    kt += w.x * ce[e] + w.y * de[e];
                }
            }
        }
        racc += (double)rt;
        kacc += (double)kt;
    }

    // ---- Phase C: block reduction ----
    #pragma unroll
    for (int off = 16; off > 0; off >>= 1) {
        racc += __shfl_down_sync(0xFFFFFFFFu, racc, off);
        kacc += __shfl_down_sync(0xFFFFFFFFu, kacc, off);
        c    += __shfl_down_sync(0xFFFFFFFFu, c,    off);
    }

    __shared__ double s_r[8], s_k[8];
    __shared__ int    s_c[8];
    int wid = tid >> 5;
    int lid = tid & 31;
    if (lid == 0) { s_r[wid] = racc; s_k[wid] = kacc; s_c[wid] = c; }
    __syncthreads();

    if (wid == 0) {
        double br = (lid < 8) ? s_r[lid] : 0.0;
        double bk = (lid < 8) ? s_k[lid] : 0.0;
        int    bc = (lid < 8) ? s_c[lid] : 0;
        #pragma unroll
        for (int off = 4; off > 0; off >>= 1) {
            br += __shfl_down_sync(0xFFFFFFFFu, br, off);
            bk += __shfl_down_sync(0xFFFFFFFFu, bk, off);
            bc += __shfl_down_sync(0xFFFFFFFFu, bc, off);
        }
        if (lid == 0) {
            atomicAdd(&g_acc[0], br);
            atomicAdd(&g_acc[1], bk);
            if (bc) atomicAdd(&g_count, bc);
        }
    }

    // ---- Phase D: last-block finalize + reset ----
    __shared__ bool is_last;
    if (tid == 0) {
        __threadfence();
        unsigned tkt = atomicAdd(&g_done, 1u);
        is_last = (tkt == gridDim.x - 1);
    }
    __syncthreads();
    if (is_last && tid == 0) {
        __threadfence();
        double vr = g_acc[0];
        double vk = g_acc[1];
        int    vc = g_count;
        if (out_size > 0) out[0] = (float)(vr / 154.0);
        if (out_size > 1) out[1] = (float)vk;
        if (out_size > 2) out[2] = (float)vc;
        g_acc[0] = 0.0;
        g_acc[1] = 0.0;
        g_count  = 0;
        __threadfence();
        g_done   = 0;
    }
}

extern "C" void kernel_launch(void* const* d_in, const int* in_sizes, int n_in,
                              void* d_out, int out_size) {
    const float4* rl = (const float4*)d_in[0];
    const float4* rr = (const float4*)d_in[1];
    const float4* kl = (const float4*)d_in[2];
    const float4* kr = (const float4*)d_in[3];
    const int* lr    = (const int*)d_in[4];
    const int* fpose = (const int*)d_in[5];
    float* out = (float*)d_out;

    fused_pose_loss<<<GRID_BLOCKS, BLOCK_THREADS>>>(rl, rr, kl, kr, lr, fpose,
                                                    out, out_size);
}

// round 16
// speedup vs baseline: 2.5909x; 2.0909x over previous
#include <cuda_runtime.h>
#include <cstdint>

// Problem constants (Pose_Loss: B=65536, D=154)
#define BB   65536
#define DD   154
#define D2   77                     // floats2 per row (154/2), rows 8B-aligned

#define BLOCK_THREADS 256
#define WARPS_PER_BLOCK 8
#define GRID_BLOCKS 512
#define TOTAL_WARPS (GRID_BLOCKS * WARPS_PER_BLOCK)   // 4096
#define RPW (BB / TOTAL_WARPS)                        // 16 rows per warp
static_assert(BB == TOTAL_WARPS * RPW, "exact row partition");

// Scratch (allocation-free device globals; zero at load, re-zeroed each exec)
__device__ double        g_acc[2];   // [0]=recon, [1]=KLD
__device__ int           g_count;
__device__ unsigned int  g_done;

__device__ __forceinline__ void l2_prefetch(const void* p) {
    asm volatile("prefetch.global.L2 [%0];" :: "l"(p));
}

__global__ void __launch_bounds__(BLOCK_THREADS)
fused_pose_loss(const float2* __restrict__ rl, const float2* __restrict__ rr,
                const float2* __restrict__ kl, const float2* __restrict__ kr,
                const int* __restrict__ lr,    const int* __restrict__ fpose,
                float* __restrict__ out, int out_size) {
    const int tid  = threadIdx.x;
    const int lane = tid & 31;
    const int wid  = tid >> 5;
    const unsigned gtid = blockIdx.x * BLOCK_THREADS + tid;

    // ---- Phase A: per-row count (512*256 = 131,072 threads > BB) ----
    int c = 0;
    if (gtid < BB) {
        int l = lr[gtid];
        if (fpose[gtid] != -1)
            c = (l != 1 ? 1 : 0) + (l != 0 ? 1 : 0);
    }

    // ---- Phase B: warp-per-row, mask-gated loads (skip dead rows) ----
    const unsigned r0 = (blockIdx.x * WARPS_PER_BLOCK + wid) * RPW;

    float racc_f = 0.0f, kacc_f = 0.0f;

    // software-pipelined masks (warp-uniform broadcast loads)
    int l_cur = lr[r0];
    int f_cur = fpose[r0];

    #pragma unroll
    for (int j = 0; j < RPW; j++) {
        const unsigned r = r0 + j;

        // next row's masks + predicated prefetch of its data
        bool wl_n = false, wr_n = false;
        if (j + 1 < RPW) {
            int l_n = lr[r + 1];
            int f_n = fpose[r + 1];
            bool valid_n = (f_n != -1);
            wl_n = valid_n && (l_n != 1);
            wr_n = valid_n && (l_n != 0);
            if (lane < 6) {   // 6 lines cover a 616B row at any alignment
                size_t ofs = (size_t)(r + 1) * (DD * 4) + lane * 128;
                if (wl_n) {
                    l2_prefetch((const char*)rl + ofs);
                    l2_prefetch((const char*)kl + ofs);
                }
                if (wr_n) {
                    l2_prefetch((const char*)rr + ofs);
                    l2_prefetch((const char*)kr + ofs);
                }
            }
        }

        bool valid = (f_cur != -1);
        bool wl = valid && (l_cur != 1);
        bool wr = valid && (l_cur != 0);

        if (wl || wr) {
            const unsigned b2 = r * D2;
            const int i0 = lane, i1 = lane + 32, i2 = lane + 64;
            const bool p2 = (i2 < D2);   // lanes 0..12 on 3rd wave

            if (wl) {   // warp-uniform
                float2 a0 = rl[b2 + i0];
                float2 a1 = rl[b2 + i1];
                float2 c0 = kl[b2 + i0];
                float2 c1 = kl[b2 + i1];
                float2 a2 = p2 ? rl[b2 + i2] : make_float2(0.f, 0.f);
                float2 c2 = p2 ? kl[b2 + i2] : make_float2(0.f, 0.f);
                racc_f += (a0.x + a0.y) + (a1.x + a1.y) + (a2.x + a2.y);
                kacc_f += (c0.x + c0.y) + (c1.x + c1.y) + (c2.x + c2.y);
            }
            if (wr) {   // warp-uniform
                float2 b0 = rr[b2 + i0];
                float2 b1 = rr[b2 + i1];
                float2 d0 = kr[b2 + i0];
                float2 d1 = kr[b2 + i1];
                float2 b2v = p2 ? rr[b2 + i2] : make_float2(0.f, 0.f);
                float2 d2v = p2 ? kr[b2 + i2] : make_float2(0.f, 0.f);
                racc_f += (b0.x + b0.y) + (b1.x + b1.y) + (b2v.x + b2v.y);
                kacc_f += (d0.x + d0.y) + (d1.x + d1.y) + (d2v.x + d2v.y);
            }
        }

        l_cur = wl_n || wr_n || j + 1 >= RPW ? l_cur : l_cur; // keep regs simple
        if (j + 1 < RPW) {
            l_cur = lr[r + 1];      // L1-hit (just loaded above)
            f_cur = fpose[r + 1];
        }
    }

    double racc = (double)racc_f;
    double kacc = (double)kacc_f;

    // ---- Phase C: block reduction ----
    #pragma unroll
    for (int off = 16; off > 0; off >>= 1) {
        racc += __shfl_down_sync(0xFFFFFFFFu, racc, off);
        kacc += __shfl_down_sync(0xFFFFFFFFu, kacc, off);
        c    += __shfl_down_sync(0xFFFFFFFFu, c,    off);
    }

    __shared__ double s_r[8], s_k[8];
    __shared__ int    s_c[8];
    if (lane == 0) { s_r[wid] = racc; s_k[wid] = kacc; s_c[wid] = c; }
    __syncthreads();

    if (wid == 0) {
        double br = (lane < 8) ? s_r[lane] : 0.0;
        double bk = (lane < 8) ? s_k[lane] : 0.0;
        int    bc = (lane < 8) ? s_c[lane] : 0;
        #pragma unroll
        for (int off = 4; off > 0; off >>= 1) {
            br += __shfl_down_sync(0xFFFFFFFFu, br, off);
            bk += __shfl_down_sync(0xFFFFFFFFu, bk, off);
            bc += __shfl_down_sync(0xFFFFFFFFu, bc, off);
        }
        if (lane == 0) {
            atomicAdd(&g_acc[0], br);
            atomicAdd(&g_acc[1], bk);
            if (bc) atomicAdd(&g_count, bc);
        }
    }

    // ---- Phase D: last-block finalize + reset ----
    __shared__ bool is_last;
    if (tid == 0) {
        __threadfence();
        unsigned tkt = atomicAdd(&g_done, 1u);
        is_last = (tkt == gridDim.x - 1);
    }
    __syncthreads();
    if (is_last && tid == 0) {
        __threadfence();
        double vr = g_acc[0];
        double vk = g_acc[1];
        int    vc = g_count;
        if (out_size > 0) out[0] = (float)(vr / 154.0);
        if (out_size > 1) out[1] = (float)vk;
        if (out_size > 2) out[2] = (float)vc;
        g_acc[0] = 0.0;
        g_acc[1] = 0.0;
        g_count  = 0;
        __threadfence();
        g_done   = 0;
    }
}

extern "C" void kernel_launch(void* const* d_in, const int* in_sizes, int n_in,
                              void* d_out, int out_size) {
    const float2* rl = (const float2*)d_in[0];
    const float2* rr = (const float2*)d_in[1];
    const float2* kl = (const float2*)d_in[2];
    const float2* kr = (const float2*)d_in[3];
    const int* lr    = (const int*)d_in[4];
    const int* fpose = (const int*)d_in[5];
    float* out = (float*)d_out;

    fused_pose_loss<<<GRID_BLOCKS, BLOCK_THREADS>>>(rl, rr, kl, kr, lr, fpose,
                                                    out, out_size);
}